// round 2
// baseline (speedup 1.0000x reference)
#include <cuda_runtime.h>

// UpFIRDn2d fused kernel:
// crop(1) -> +bias -> up x2 (nearest/repeat) -> sep conv up_filter (K=12, same)
// -> leaky(0.2)*sqrt(2) -> sep conv dn_filter (K=12, same) -> down x2 (::2)
//
// Polyphase: repeat-by-2 followed by 12-tap correlation (pl=5) on the
// original-rate signal:
//   even out y[2m]   : taps e[0..6] on x[m-3..m+3], e = {f0, f1+f2, f3+f4, f5+f6, f7+f8, f9+f10, f11}
//   odd  out y[2m+1] : taps o[0..5] on x[m-2..m+3], o = {f0+f1, f2+f3, f4+f5, f6+f7, f8+f9, f10+f11}
// Down-by-2 after dn-conv == stride-2 12-tap sampling (compute kept samples only).
// IMPORTANT: y is only valid on [0,256) per axis; the dn-conv zero-pads beyond
// that, so intermediates at out-of-range upsampled coords must be ZERO.

#define NTHR 256
#define TH 32
#define TW 32

// Shared memory layout (floats), regions reused across stages:
//   region A: s_x  [43][45] = 1935   then  t2 [74][33] = 2442
//   region B: t1   [43][75] = 3225
//   region C: a    [74][75] = 5550
#define SM_A 2442
#define SM_B 3225
#define SM_C 5550
#define SM_TOTAL (SM_A + SM_B + SM_C)   // 11217 floats = 44.87 KB

__global__ __launch_bounds__(NTHR, 4)
void upfirdn2d_fused_kernel(const float* __restrict__ x,
                            const float* __restrict__ bias,
                            const float* __restrict__ fup,
                            const float* __restrict__ fdn,
                            float* __restrict__ out)
{
    __shared__ float smem[SM_TOTAL];
    float* s_x  = smem;                 // [43][45], 44 cols used
    float* s_t2 = smem;                 // [74][33], 32 cols used (aliases s_x)
    float* s_t1 = smem + SM_A;          // [43][75], 74 cols used
    float* s_a  = smem + SM_A + SM_B;   // [74][75], 74 cols used

    const int tid = threadIdx.x;
    const int bc  = blockIdx.y;          // 0..511 (b*64 + c)
    const int c   = bc & 63;
    const int Y0  = (blockIdx.x >> 2) * TH;
    const int X0  = (blockIdx.x & 3)  * TW;

    // ---- filters in registers; build polyphase taps for the up filter ----
    float up[12], dn[12];
    #pragma unroll
    for (int k = 0; k < 12; k++) { up[k] = fup[k]; dn[k] = fdn[k]; }
    float e[7], o[6];
    e[0] = up[0]; e[6] = up[11];
    #pragma unroll
    for (int j = 1; j < 6; j++) e[j] = up[2*j - 1] + up[2*j];
    #pragma unroll
    for (int j = 0; j < 6; j++) o[j] = up[2*j] + up[2*j + 1];

    const float bv = bias[c];
    const float* xin = x + (size_t)bc * (130 * 130);

    // ---- Stage 0: load input tile with halo, zero-padded, bias added ----
    // s_x[r][cc]: global row gy = Y0-5+r (r in [0,43)), col gx = X0-6+cc (cc in [0,44))
    for (int idx = tid; idx < 43 * 44; idx += NTHR) {
        int r  = idx / 44;
        int cc = idx - r * 44;
        int gy = Y0 - 5 + r;
        int gx = X0 - 6 + cc;
        float v = 0.0f;
        if ((unsigned)gy < 128u && (unsigned)gx < 128u)
            v = xin[(gy + 1) * 130 + (gx + 1)] + bv;
        s_x[r * 45 + cc] = v;
    }
    __syncthreads();

    // ---- Stage 1: horizontal polyphase up-conv -> t1[43][74] ----
    // t1[r][ac] = up-conv of x row r at upsampled col gc = 2*X0-5+ac.
    // y is only defined for gc in [0,256); outside it is dn-conv zero padding.
    for (int idx = tid; idx < 43 * 74; idx += NTHR) {
        int r  = idx / 74;
        int ac = idx - r * 74;
        int gc = 2 * X0 - 5 + ac;
        float v = 0.0f;
        if ((unsigned)gc < 256u) {
            int q  = gc >> 1;            // floor div 2
            int cx = q - X0 + 6;         // local col in s_x of x[q]
            const float* row = s_x + r * 45;
            if (gc & 1) {
                v = o[0]*row[cx-2] + o[1]*row[cx-1] + o[2]*row[cx]
                  + o[3]*row[cx+1] + o[4]*row[cx+2] + o[5]*row[cx+3];
            } else {
                v = e[0]*row[cx-3] + e[1]*row[cx-2] + e[2]*row[cx-1] + e[3]*row[cx]
                  + e[4]*row[cx+1] + e[5]*row[cx+2] + e[6]*row[cx+3];
            }
        }
        s_t1[r * 75 + ac] = v;
    }
    __syncthreads();

    // ---- Stage 2: vertical polyphase up-conv + leaky*gain -> a[74][74] ----
    // a[ar][ac] at upsampled row gr = 2*Y0-5+ar; zero outside gr in [0,256).
    for (int idx = tid; idx < 74 * 74; idx += NTHR) {
        int ar = idx / 74;
        int ac = idx - ar * 74;
        int gr = 2 * Y0 - 5 + ar;
        float res = 0.0f;
        if ((unsigned)gr < 256u) {
            int p  = gr >> 1;
            int tr = p - Y0 + 5;         // local row in t1 of x row p
            const float* col = s_t1 + ac;
            float v;
            if (gr & 1) {
                v = o[0]*col[(tr-2)*75] + o[1]*col[(tr-1)*75] + o[2]*col[tr*75]
                  + o[3]*col[(tr+1)*75] + o[4]*col[(tr+2)*75] + o[5]*col[(tr+3)*75];
            } else {
                v = e[0]*col[(tr-3)*75] + e[1]*col[(tr-2)*75] + e[2]*col[(tr-1)*75]
                  + e[3]*col[tr*75]     + e[4]*col[(tr+1)*75] + e[5]*col[(tr+2)*75]
                  + e[6]*col[(tr+3)*75];
            }
            float g = v * 1.41421356237309515f;
            res = (v >= 0.0f) ? g : 0.2f * g;
        }
        s_a[ar * 75 + ac] = res;
    }
    __syncthreads();

    // ---- Stage 3: horizontal dn-conv, stride-2 sampling -> t2[74][32] ----
    // t2[ar][Xl] = sum_k dn[k] * a[ar][2*Xl + k]   (a col 0 == upsampled col 2*X0-5)
    for (int idx = tid; idx < 74 * 32; idx += NTHR) {
        int ar = idx >> 5;
        int Xl = idx & 31;
        const float* row = s_a + ar * 75 + 2 * Xl;
        float v = 0.0f;
        #pragma unroll
        for (int k = 0; k < 12; k++) v += dn[k] * row[k];
        s_t2[ar * 33 + Xl] = v;
    }
    __syncthreads();

    // ---- Stage 4: vertical dn-conv, stride-2 sampling -> out[32][32] ----
    for (int idx = tid; idx < 32 * 32; idx += NTHR) {
        int Yl = idx >> 5;
        int Xl = idx & 31;
        const float* col = s_t2 + (2 * Yl) * 33 + Xl;
        float v = 0.0f;
        #pragma unroll
        for (int k = 0; k < 12; k++) v += dn[k] * col[k * 33];
        out[((size_t)bc * 128 + (Y0 + Yl)) * 128 + (X0 + Xl)] = v;
    }
}

extern "C" void kernel_launch(void* const* d_in, const int* in_sizes, int n_in,
                              void* d_out, int out_size)
{
    const float* x    = (const float*)d_in[0];   // (8,64,130,130) fp32
    const float* bias = (const float*)d_in[1];   // (64,) fp32
    const float* fup  = (const float*)d_in[2];   // (12,) fp32
    const float* fdn  = (const float*)d_in[3];   // (12,) fp32
    float* out = (float*)d_out;                  // (8,64,128,128) fp32

    dim3 grid(16, 512);   // 16 tiles (4x4 of 32x32) per channel-image, 512 channel-images
    upfirdn2d_fused_kernel<<<grid, NTHR>>>(x, bias, fup, fdn, out);
}

// round 3
// speedup vs baseline: 1.9947x; 1.9947x over previous
#include <cuda_runtime.h>

// Fully fused UpFIRDn2d (crop -> bias -> up2 -> sep FIR -> leaky*sqrt2 -> sep FIR -> dn2)
// Polyphase up-conv taps (12-tap filter f, pl=5 correlation):
//   y[2m]   = sum_{k=0..6} e[k]*x[m-3+k],  e = {f0, f1+f2, f3+f4, f5+f6, f7+f8, f9+f10, f11}
//   y[2m+1] = sum_{k=0..5} o[k]*x[m-2+k],  o = {f0+f1, f2+f3, f4+f5, f6+f7, f8+f9, f10+f11}
// y only valid on [0,256) per axis (dn-conv zero-pads beyond) -> force 0 outside.
// Phase pairing: outputs (ac=2j, ac=2j+1) share window x[local j+1 .. j+7].

#define NTHR 256

// smem regions (floats):
//   A: s_x [43][45] = 1935, later t2 [74][34] = 2516
//   B: t1  [43][76] = 3268   (pitch 76 -> even, STS.64-aligned)
//   C: a   [74][76] = 5624   (pitch 76 -> float2-aligned rows)
#define SM_A 2516
#define SM_B 3268
#define SM_C 5624
#define SM_TOTAL (SM_A + SM_B + SM_C)   // 11408 floats = 45.6 KB

__global__ __launch_bounds__(NTHR, 4)
void upfirdn2d_fused_kernel(const float* __restrict__ x,
                            const float* __restrict__ bias,
                            const float* __restrict__ fup,
                            const float* __restrict__ fdn,
                            float* __restrict__ out)
{
    __shared__ float smem[SM_TOTAL];
    float* s_x  = smem;                  // pitch 45
    float* s_t2 = smem;                  // pitch 34 (aliases s_x; reused after S1)
    float* s_t1 = smem + SM_A;           // pitch 76
    float* s_a  = smem + SM_A + SM_B;    // pitch 76

    const int tid = threadIdx.x;
    const int bc  = blockIdx.y;                 // b*64 + c
    const int Y0  = (blockIdx.x >> 2) * 32;
    const int X0  = (blockIdx.x & 3)  * 32;

    // ---- polyphase up taps (only e,o stay live through S1/S2) ----
    float e[7], o[6];
    {
        float up[12];
        #pragma unroll
        for (int k = 0; k < 12; k++) up[k] = fup[k];
        e[0] = up[0]; e[6] = up[11];
        #pragma unroll
        for (int j = 1; j < 6; j++) e[j] = up[2*j - 1] + up[2*j];
        #pragma unroll
        for (int j = 0; j < 6; j++) o[j] = up[2*j] + up[2*j + 1];
    }
    const float bv = bias[bc & 63];
    const float* xin = x + (size_t)bc * (130 * 130);

    // ---- S0: load input tile + halo (43 x 44), bias added, zero pad ----
    {
        const int lane = tid & 31, w = tid >> 5;
        #pragma unroll
        for (int rr = 0; rr < 6; rr++) {
            int r = w + 8 * rr;
            if (r < 43) {
                int gy = Y0 - 5 + r;
                bool rowok = (unsigned)gy < 128u;
                const float* src = xin + (gy + 1) * 130 + (X0 - 5);
                float* dst = s_x + r * 45;
                #pragma unroll
                for (int ci = 0; ci < 2; ci++) {
                    int cc = lane + 32 * ci;
                    if (cc < 44) {
                        int gx = X0 - 6 + cc;
                        float v = 0.0f;
                        if (rowok && (unsigned)gx < 128u) v = src[cc] + bv;
                        dst[cc] = v;
                    }
                }
            }
        }
    }
    __syncthreads();

    // ---- S1: horizontal polyphase up -> t1[43][74], paired outputs ----
    // pair j (0..36), row r (0..42): window w[k] = s_x[r][j+1+k], k=0..6
    //   ac=2j   (gc = 2X0-5+2j, odd phase):  o[0..5] . w[0..5]
    //   ac=2j+1 (gc+1, even phase):          e[0..6] . w[0..6]
    #pragma unroll
    for (int t = 0; t < 7; t++) {
        int u = tid + 256 * t;
        if (u < 43 * 37) {
            int r = u / 37;
            int j = u - r * 37;
            const float* row = s_x + r * 45 + j;
            float w0 = row[1], w1 = row[2], w2 = row[3], w3 = row[4],
                  w4 = row[5], w5 = row[6], w6 = row[7];
            int gc = 2 * X0 - 5 + 2 * j;
            float vo = 0.0f, ve = 0.0f;
            if ((unsigned)gc < 256u)
                vo = o[0]*w0 + o[1]*w1 + o[2]*w2 + o[3]*w3 + o[4]*w4 + o[5]*w5;
            if ((unsigned)(gc + 1) < 256u)
                ve = e[0]*w0 + e[1]*w1 + e[2]*w2 + e[3]*w3 + e[4]*w4 + e[5]*w5 + e[6]*w6;
            *reinterpret_cast<float2*>(s_t1 + r * 76 + 2 * j) = make_float2(vo, ve);
        }
    }
    __syncthreads();

    // ---- S2: vertical polyphase up + leaky*gain -> a[74][74] ----
    // pair i (0..36), col ac (0..73): window w[k] = t1[i+k][ac]
    #pragma unroll
    for (int t = 0; t < 11; t++) {
        int u = tid + 256 * t;
        if (u < 37 * 74) {
            int i  = u / 74;
            int ac = u - i * 74;
            const float* col = s_t1 + i * 76 + ac;
            float w0 = col[0],     w1 = col[76],    w2 = col[152], w3 = col[228],
                  w4 = col[304],   w5 = col[380],   w6 = col[456];
            int gr = 2 * Y0 - 5 + 2 * i;
            float vo = 0.0f, ve = 0.0f;
            if ((unsigned)gr < 256u)
                vo = o[0]*w0 + o[1]*w1 + o[2]*w2 + o[3]*w3 + o[4]*w4 + o[5]*w5;
            if ((unsigned)(gr + 1) < 256u)
                ve = e[0]*w0 + e[1]*w1 + e[2]*w2 + e[3]*w3 + e[4]*w4 + e[5]*w5 + e[6]*w6;
            float go = vo * 1.41421356237309515f;
            float ge = ve * 1.41421356237309515f;
            s_a[(2*i)     * 76 + ac] = (vo >= 0.0f) ? go : 0.2f * go;
            s_a[(2*i + 1) * 76 + ac] = (ve >= 0.0f) ? ge : 0.2f * ge;
        }
    }
    __syncthreads();

    // dn filter loaded here so its registers don't overlap e/o liveness
    float dn[12];
    #pragma unroll
    for (int k = 0; k < 12; k++) dn[k] = fdn[k];

    // ---- S3: horizontal dn-conv, stride-2 -> t2[74][32], 2 outputs/unit ----
    // unit (ar, p): outputs X=2p,2p+1; reads a[ar][4p .. 4p+13] as 7 float2
    #pragma unroll
    for (int t = 0; t < 5; t++) {
        int u = tid + 256 * t;
        if (u < 74 * 16) {
            int ar = u >> 4;
            int p  = u & 15;
            const float2* row = reinterpret_cast<const float2*>(s_a + ar * 76 + 4 * p);
            float2 q0 = row[0], q1 = row[1], q2 = row[2], q3 = row[3],
                   q4 = row[4], q5 = row[5], q6 = row[6];
            float v0 = dn[0]*q0.x + dn[1]*q0.y + dn[2]*q1.x + dn[3]*q1.y
                     + dn[4]*q2.x + dn[5]*q2.y + dn[6]*q3.x + dn[7]*q3.y
                     + dn[8]*q4.x + dn[9]*q4.y + dn[10]*q5.x + dn[11]*q5.y;
            float v1 = dn[0]*q1.x + dn[1]*q1.y + dn[2]*q2.x + dn[3]*q2.y
                     + dn[4]*q3.x + dn[5]*q3.y + dn[6]*q4.x + dn[7]*q4.y
                     + dn[8]*q5.x + dn[9]*q5.y + dn[10]*q6.x + dn[11]*q6.y;
            *reinterpret_cast<float2*>(s_t2 + ar * 34 + 2 * p) = make_float2(v0, v1);
        }
    }
    __syncthreads();

    // ---- S4: vertical dn-conv, stride-2 -> out, 4 outputs per thread ----
    {
        int Xl = tid & 31;
        int y0 = (tid >> 5) * 4;
        const float* col = s_t2 + (2 * y0) * 34 + Xl;
        float r[18];
        #pragma unroll
        for (int k = 0; k < 18; k++) r[k] = col[k * 34];
        float* op = out + ((size_t)bc * 128 + (Y0 + y0)) * 128 + X0 + Xl;
        #pragma unroll
        for (int q = 0; q < 4; q++) {
            float v = 0.0f;
            #pragma unroll
            for (int k = 0; k < 12; k++) v += dn[k] * r[2*q + k];
            op[q * 128] = v;
        }
    }
}

extern "C" void kernel_launch(void* const* d_in, const int* in_sizes, int n_in,
                              void* d_out, int out_size)
{
    const float* x    = (const float*)d_in[0];   // (8,64,130,130) fp32
    const float* bias = (const float*)d_in[1];   // (64,) fp32
    const float* fup  = (const float*)d_in[2];   // (12,) fp32
    const float* fdn  = (const float*)d_in[3];   // (12,) fp32
    float* out = (float*)d_out;                  // (8,64,128,128) fp32

    dim3 grid(16, 512);
    upfirdn2d_fused_kernel<<<grid, NTHR>>>(x, bias, fup, fdn, out);
}

// round 4
// speedup vs baseline: 2.5304x; 1.2686x over previous
#include <cuda_runtime.h>

// Fully fused UpFIRDn2d (crop -> bias -> up2 -> sep FIR12 -> leaky*sqrt2 -> sep FIR12 -> dn2)
// Polyphase up taps (pl=5 correlation):
//   y[2m]   = sum e[k]*x[m-3+k] (k=0..6), e = {f0, f1+f2, f3+f4, f5+f6, f7+f8, f9+f10, f11}
//   y[2m+1] = sum o[k]*x[m-2+k] (k=0..5), o = {f0+f1, f2+f3, f4+f5, f6+f7, f8+f9, f10+f11}
// y valid only on [0,256) per axis (dn-conv zero-pads beyond) -> force 0 outside.
//
// SMEM lifetimes allow heavy aliasing:
//   region A [0,5624):      s_x (43 x p46 = 1978) during S0/S1; a (74 x p76 = 5624) during S2/S3
//   region B [5624,9120):   t1 (46 x p76 = 3496, rows 43..45 pad) S1/S2; t2 (74 x p36 = 2664) S3/S4
// Total 9120 floats = 36.5 KB -> 5+ CTAs/SM.

#define NTHR 256
#define PX  46   // s_x pitch
#define PT  76   // t1 / a pitch
#define P2  36   // t2 pitch
#define T1_OFF 5624
#define SM_TOTAL (5624 + 46 * PT)   // 9120 floats

__global__ __launch_bounds__(NTHR, 5)
void upfirdn2d_fused_kernel(const float* __restrict__ x,
                            const float* __restrict__ bias,
                            const float* __restrict__ fup,
                            const float* __restrict__ fdn,
                            float* __restrict__ out)
{
    __shared__ float smem[SM_TOTAL];
    float* s_x  = smem;             // pitch 46 (S0-S1)
    float* s_a  = smem;             // pitch 76 (S2-S3), aliases s_x
    float* s_t1 = smem + T1_OFF;    // pitch 76 (S1-S2)
    float* s_t2 = smem + T1_OFF;    // pitch 36 (S3-S4), aliases t1

    const int tid = threadIdx.x;
    const int bc  = blockIdx.y;
    const int Y0  = (blockIdx.x >> 2) * 32;
    const int X0  = (blockIdx.x & 3)  * 32;

    // polyphase up taps
    float e[7], o[6];
    {
        float up[12];
        #pragma unroll
        for (int k = 0; k < 12; k++) up[k] = fup[k];
        e[0] = up[0]; e[6] = up[11];
        #pragma unroll
        for (int j = 1; j < 6; j++) e[j] = up[2*j - 1] + up[2*j];
        #pragma unroll
        for (int j = 0; j < 6; j++) o[j] = up[2*j] + up[2*j + 1];
    }
    const float bv = bias[bc & 63];
    const float* xin = x + (size_t)bc * (130 * 130);

    // ---- S0: input tile + halo (43 x 44), bias, zero pad ----
    {
        const int lane = tid & 31, w = tid >> 5;
        #pragma unroll
        for (int rr = 0; rr < 6; rr++) {
            int r = w + 8 * rr;
            if (r < 43) {
                int gy = Y0 - 5 + r;
                bool rowok = (unsigned)gy < 128u;
                const float* src = xin + (gy + 1) * 130 + (X0 - 5);
                float* dst = s_x + r * PX;
                #pragma unroll
                for (int ci = 0; ci < 2; ci++) {
                    int cc = lane + 32 * ci;
                    if (cc < 44) {
                        int gx = X0 - 6 + cc;
                        float v = 0.0f;
                        if (rowok && (unsigned)gx < 128u) v = src[cc] + bv;
                        dst[cc] = v;
                    }
                }
            }
        }
    }
    __syncthreads();

    // ---- S1: horizontal polyphase up -> t1[43][74] ----
    // unit (r, t): pairs j=2t, 2t+1 -> t1 cols 4t..4t+3. Window x cols 2t..2t+9 (5 float2).
    #pragma unroll
    for (int it = 0; it < 4; it++) {
        int u = tid + 256 * it;
        if (u < 43 * 19) {
            int r = u / 19;
            int t = u - r * 19;
            const float2* row = reinterpret_cast<const float2*>(s_x + r * PX + 2 * t);
            float2 q0 = row[0], q1 = row[1], q2 = row[2], q3 = row[3], q4 = row[4];
            int gc = 2 * X0 - 5 + 4 * t;
            float voA = 0.f, veA = 0.f, voB = 0.f, veB = 0.f;
            if ((unsigned)gc < 256u)
                voA = o[0]*q0.y + o[1]*q1.x + o[2]*q1.y + o[3]*q2.x + o[4]*q2.y + o[5]*q3.x;
            if ((unsigned)(gc+1) < 256u)
                veA = e[0]*q0.y + e[1]*q1.x + e[2]*q1.y + e[3]*q2.x + e[4]*q2.y + e[5]*q3.x + e[6]*q3.y;
            if ((unsigned)(gc+2) < 256u)
                voB = o[0]*q1.x + o[1]*q1.y + o[2]*q2.x + o[3]*q2.y + o[4]*q3.x + o[5]*q3.y;
            if ((unsigned)(gc+3) < 256u)
                veB = e[0]*q1.x + e[1]*q1.y + e[2]*q2.x + e[3]*q2.y + e[4]*q3.x + e[5]*q3.y + e[6]*q4.x;
            float* dst = s_t1 + r * PT + 4 * t;
            if (t < 18) {
                *reinterpret_cast<float4*>(dst) = make_float4(voA, veA, voB, veB);
            } else {  // pair 37 doesn't exist
                *reinterpret_cast<float2*>(dst) = make_float2(voA, veA);
            }
        }
    }
    __syncthreads();

    // ---- S2: vertical polyphase up + leaky*gain -> a[74][74] ----
    // unit (g, ac2): col-pair (2*ac2, 2*ac2+1), row-pairs i = 4g..4g+3 (i<37).
    // Window: t1 rows 4g..4g+9 (10 float2 loads). t1 padded to 46 rows.
    #pragma unroll
    for (int it = 0; it < 2; it++) {
        int u = tid + 256 * it;
        if (u < 10 * 37) {
            int g   = u / 37;
            int ac2 = u - g * 37;
            const float* base = s_t1 + (4 * g) * PT + 2 * ac2;
            float2 W[10];
            #pragma unroll
            for (int k = 0; k < 10; k++)
                W[k] = *reinterpret_cast<const float2*>(base + k * PT);
            float* adst = s_a + (8 * g) * PT + 2 * ac2;
            #pragma unroll
            for (int p = 0; p < 4; p++) {
                int i = 4 * g + p;
                if (i < 37) {
                    int gr = 2 * Y0 - 5 + 2 * i;
                    float vox = 0.f, voy = 0.f, vex = 0.f, vey = 0.f;
                    if ((unsigned)gr < 256u) {
                        vox = o[0]*W[p].x + o[1]*W[p+1].x + o[2]*W[p+2].x
                            + o[3]*W[p+3].x + o[4]*W[p+4].x + o[5]*W[p+5].x;
                        voy = o[0]*W[p].y + o[1]*W[p+1].y + o[2]*W[p+2].y
                            + o[3]*W[p+3].y + o[4]*W[p+4].y + o[5]*W[p+5].y;
                    }
                    if ((unsigned)(gr+1) < 256u) {
                        vex = e[0]*W[p].x + e[1]*W[p+1].x + e[2]*W[p+2].x + e[3]*W[p+3].x
                            + e[4]*W[p+4].x + e[5]*W[p+5].x + e[6]*W[p+6].x;
                        vey = e[0]*W[p].y + e[1]*W[p+1].y + e[2]*W[p+2].y + e[3]*W[p+3].y
                            + e[4]*W[p+4].y + e[5]*W[p+5].y + e[6]*W[p+6].y;
                    }
                    const float G = 1.41421356237309515f;
                    float2 ro, re;
                    ro.x = (vox >= 0.f) ? vox * G : vox * (0.2f * G);
                    ro.y = (voy >= 0.f) ? voy * G : voy * (0.2f * G);
                    re.x = (vex >= 0.f) ? vex * G : vex * (0.2f * G);
                    re.y = (vey >= 0.f) ? vey * G : vey * (0.2f * G);
                    *reinterpret_cast<float2*>(adst + (2 * p)     * PT) = ro;
                    *reinterpret_cast<float2*>(adst + (2 * p + 1) * PT) = re;
                }
            }
        }
    }
    __syncthreads();

    // dn filter loaded here so its registers don't extend e/o liveness
    float dn[12];
    #pragma unroll
    for (int k = 0; k < 12; k++) dn[k] = fdn[k];

    // ---- S3: horizontal dn-conv, stride-2 -> t2[74][32], 4 outputs/unit ----
    // unit (t, ar): outputs X = 4t..4t+3; reads a[ar][8t .. 8t+19] as 5 float4.
    // ar fast-varying across lanes: pitch 76 (304B = 48 mod 128) tiles banks -> floor phases.
    #pragma unroll
    for (int it = 0; it < 3; it++) {
        int u = tid + 256 * it;
        if (u < 8 * 74) {
            int t  = u / 74;
            int ar = u - t * 74;
            const float4* row = reinterpret_cast<const float4*>(s_a + ar * PT + 8 * t);
            float4 a0 = row[0], a1 = row[1], a2 = row[2], a3 = row[3], a4 = row[4];
            float A[20] = {a0.x,a0.y,a0.z,a0.w, a1.x,a1.y,a1.z,a1.w,
                           a2.x,a2.y,a2.z,a2.w, a3.x,a3.y,a3.z,a3.w,
                           a4.x,a4.y,a4.z,a4.w};
            float v[4];
            #pragma unroll
            for (int q = 0; q < 4; q++) {
                float s = 0.f;
                #pragma unroll
                for (int k = 0; k < 12; k++) s += dn[k] * A[2*q + k];
                v[q] = s;
            }
            *reinterpret_cast<float4*>(s_t2 + ar * P2 + 4 * t) =
                make_float4(v[0], v[1], v[2], v[3]);
        }
    }
    __syncthreads();

    // ---- S4: vertical dn-conv, stride-2 -> out; 4 rows x 2 cols per thread ----
    if (tid < 128) {
        int cp = tid & 15;          // col-pair: Xl = 2*cp
        int yg = tid >> 4;          // y0 = 4*yg
        const float* base = s_t2 + (8 * yg) * P2 + 2 * cp;
        float2 R[18];
        #pragma unroll
        for (int k = 0; k < 18; k++)
            R[k] = *reinterpret_cast<const float2*>(base + k * P2);
        float* op = out + ((size_t)bc * 128 + (Y0 + 4 * yg)) * 128 + X0 + 2 * cp;
        #pragma unroll
        for (int q = 0; q < 4; q++) {
            float sx = 0.f, sy = 0.f;
            #pragma unroll
            for (int k = 0; k < 12; k++) {
                sx += dn[k] * R[2*q + k].x;
                sy += dn[k] * R[2*q + k].y;
            }
            *reinterpret_cast<float2*>(op + q * 128) = make_float2(sx, sy);
        }
    }
}

extern "C" void kernel_launch(void* const* d_in, const int* in_sizes, int n_in,
                              void* d_out, int out_size)
{
    const float* x    = (const float*)d_in[0];   // (8,64,130,130) fp32
    const float* bias = (const float*)d_in[1];   // (64,) fp32
    const float* fup  = (const float*)d_in[2];   // (12,) fp32
    const float* fdn  = (const float*)d_in[3];   // (12,) fp32
    float* out = (float*)d_out;                  // (8,64,128,128) fp32

    dim3 grid(16, 512);
    upfirdn2d_fused_kernel<<<grid, NTHR>>>(x, bias, fup, fdn, out);
}